// round 3
// baseline (speedup 1.0000x reference)
#include <cuda_runtime.h>

// Problem dims (fixed by the reference setup_inputs)
static constexpr int Bn = 16;
static constexpr int Tn = 256;
static constexpr int Nn = 2048;
static constexpr int CHn = 4;               // t-chunks per (b,n)
static constexpr int TCn = Tn / CHn;        // 64 timesteps per chunk
static constexpr int NPART = Bn * CHn;      // 64 partials per point n

static constexpr float LAMBDA_T = 0.5f;
static constexpr float LAMBDA_I = 0.1f;

// Scratch for per-(point, partial) moment sums:
// layout [n][part][13]: {count, S1p[3], S2p[3], S1g[3], S2g[3]}
__device__ float g_scratch[Nn * NPART * 13];
// Global accumulators: {recon_sum, nvis, temp_sum, nvel, id_sum}
__device__ double g_acc[5];

__global__ void k_zero() {
    if (threadIdx.x < 5) g_acc[threadIdx.x] = 0.0;
}

__global__ __launch_bounds__(256) void k_main(const float* __restrict__ pred,
                                              const float* __restrict__ gt,
                                              const float* __restrict__ vis) {
    int g     = blockIdx.x * 256 + threadIdx.x;   // 0 .. B*N*CH-1
    int n     = g & (Nn - 1);                     // point id (fastest -> coalesced)
    int part  = g >> 11;                          // 0 .. 63  (= b*CH + chunk)
    int b     = part >> 2;
    int chunk = part & 3;
    int t0    = chunk * TCn;

    float recon = 0.f, cvis = 0.f, temp = 0.f, cvel = 0.f;
    float s1p0 = 0.f, s1p1 = 0.f, s1p2 = 0.f;
    float s2p0 = 0.f, s2p1 = 0.f, s2p2 = 0.f;
    float s1g0 = 0.f, s1g1 = 0.f, s1g2 = 0.f;
    float s2g0 = 0.f, s2g1 = 0.f, s2g2 = 0.f;

    // previous-frame state for the velocity term
    float pp0 = 0.f, pp1 = 0.f, pp2 = 0.f;
    float pg0 = 0.f, pg1 = 0.f, pg2 = 0.f;
    float pm  = 0.f;

    int base = (b * Tn + t0) * Nn + n;
    if (chunk != 0) {
        int ip = base - Nn;                       // frame t0-1 (chunk seam)
        pm  = vis[ip] > 0.5f ? 1.f : 0.f;
        pp0 = pred[ip * 3 + 0]; pp1 = pred[ip * 3 + 1]; pp2 = pred[ip * 3 + 2];
        pg0 = gt[ip * 3 + 0];   pg1 = gt[ip * 3 + 1];   pg2 = gt[ip * 3 + 2];
    }

    #pragma unroll 4
    for (int t = 0; t < TCn; ++t) {
        int idx = base + t * Nn;
        float m  = vis[idx] > 0.5f ? 1.f : 0.f;
        float p0 = pred[idx * 3 + 0], p1 = pred[idx * 3 + 1], p2 = pred[idx * 3 + 2];
        float q0 = gt[idx * 3 + 0],   q1 = gt[idx * 3 + 1],   q2 = gt[idx * 3 + 2];

        // reconstruction: coord weights (1,1,2), masked
        float d0 = p0 - q0, d1 = p1 - q1, d2 = p2 - q2;
        recon += m * (d0 * d0 + d1 * d1 + 2.f * d2 * d2);
        cvis  += m;

        // temporal: velocity MSE, mask = visible in both frames
        float vm = m * pm;
        float v0 = (p0 - pp0) - (q0 - pg0);
        float v1 = (p1 - pp1) - (q1 - pg1);
        float v2 = (p2 - pp2) - (q2 - pg2);
        temp += vm * (v0 * v0 + v1 * v1 + v2 * v2);
        cvel += vm;

        // identity: masked first & second moments per coord
        float mp0 = m * p0, mp1 = m * p1, mp2 = m * p2;
        float mq0 = m * q0, mq1 = m * q1, mq2 = m * q2;
        s1p0 += mp0; s1p1 += mp1; s1p2 += mp2;
        s2p0 += mp0 * p0; s2p1 += mp1 * p1; s2p2 += mp2 * p2;
        s1g0 += mq0; s1g1 += mq1; s1g2 += mq2;
        s2g0 += mq0 * q0; s2g1 += mq1 * q1; s2g2 += mq2 * q2;

        pp0 = p0; pp1 = p1; pp2 = p2;
        pg0 = q0; pg1 = q1; pg2 = q2;
        pm  = m;
    }

    // write per-(n, part) moment partials
    float* sc = g_scratch + (n * NPART + part) * 13;
    sc[0]  = cvis;
    sc[1]  = s1p0; sc[2]  = s1p1; sc[3]  = s1p2;
    sc[4]  = s2p0; sc[5]  = s2p1; sc[6]  = s2p2;
    sc[7]  = s1g0; sc[8]  = s1g1; sc[9]  = s1g2;
    sc[10] = s2g0; sc[11] = s2g1; sc[12] = s2g2;

    // block reduce (recon, cvis, temp, cvel) -> one double atomic each per block
    int lane = threadIdx.x & 31, w = threadIdx.x >> 5;
    #pragma unroll
    for (int o = 16; o; o >>= 1) {
        recon += __shfl_down_sync(0xffffffffu, recon, o);
        cvis  += __shfl_down_sync(0xffffffffu, cvis,  o);
        temp  += __shfl_down_sync(0xffffffffu, temp,  o);
        cvel  += __shfl_down_sync(0xffffffffu, cvel,  o);
    }
    __shared__ float sm[4][8];
    if (lane == 0) { sm[0][w] = recon; sm[1][w] = cvis; sm[2][w] = temp; sm[3][w] = cvel; }
    __syncthreads();
    if (threadIdx.x == 0) {
        double r = 0.0, c = 0.0, tp = 0.0, cv = 0.0;
        #pragma unroll
        for (int i = 0; i < 8; ++i) {
            r  += (double)sm[0][i];
            c  += (double)sm[1][i];
            tp += (double)sm[2][i];
            cv += (double)sm[3][i];
        }
        atomicAdd(&g_acc[0], r);
        atomicAdd(&g_acc[1], c);
        atomicAdd(&g_acc[2], tp);
        atomicAdd(&g_acc[3], cv);
    }
}

// One warp per point n: reduce 64 moment partials, compute variance ratio.
__global__ __launch_bounds__(256) void k_id() {
    int nidx = (blockIdx.x * 256 + threadIdx.x) >> 5;   // point id, 0..2047
    int lane = threadIdx.x & 31;

    const float* sc  = g_scratch + (nidx * NPART + lane) * 13;
    const float* sc2 = sc + 32 * 13;
    double a[13];
    #pragma unroll
    for (int j = 0; j < 13; ++j)
        a[j] = (double)sc[j] + (double)sc2[j];

    #pragma unroll
    for (int o = 16; o; o >>= 1) {
        #pragma unroll
        for (int j = 0; j < 13; ++j)
            a[j] += __shfl_down_sync(0xffffffffu, a[j], o);
    }

    if (lane == 0) {
        double cnt = a[0];
        if (cnt > 1.5) {   // n > 1 condition (cnt is integer-valued)
            double num = 0.0, den = 0.0;
            #pragma unroll
            for (int c = 0; c < 3; ++c) {
                double mp  = a[1 + c] / cnt;
                double ssp = a[4 + c] - a[1 + c] * mp;
                double pv  = ssp / (cnt - 1.0);
                double mg  = a[7 + c] / cnt;
                double ssg = a[10 + c] - a[7 + c] * mg;
                double gv  = ssg / (cnt - 1.0);
                num += fabs(pv - gv);
                den += gv;
            }
            atomicAdd(&g_acc[4], num / (den + 1e-6));
        }
    }
}

__global__ void k_final(float* __restrict__ out) {
    double nvis = g_acc[1], nvel = g_acc[3];
    float recon    = (nvis > 0.0) ? (float)(g_acc[0] / fmax(nvis, 1.0)) : 0.f;
    float temporal = (nvel > 0.0) ? (float)(g_acc[2] / fmax(nvel, 1.0)) : 0.f;
    float identity = (float)(g_acc[4] / (double)Nn);

    // adaptive re-weighting (faithful to reference; inert when max_comp > 0)
    float rl = recon, tl = temporal, il = identity;
    bool  all_pos = (rl > 0.f) && (tl > 0.f) && (il > 0.f);
    float maxc    = fmaxf(rl, fmaxf(tl, il));
    float target  = maxc / 3.f;
    float thresh  = 10.f * target;
    float rw = (all_pos && rl > thresh) ? 1.f      * target / fmaxf(rl, 1e-30f) : 1.f;
    float tw = (all_pos && tl > thresh) ? LAMBDA_T * target / fmaxf(tl, 1e-30f) : LAMBDA_T;
    float iw = (all_pos && il > thresh) ? LAMBDA_I * target / fmaxf(il, 1e-30f) : LAMBDA_I;

    out[0] = rw * rl + tw * tl + iw * il;
    out[1] = recon;
    out[2] = temporal;
    out[3] = identity;
}

extern "C" void kernel_launch(void* const* d_in, const int* in_sizes, int n_in,
                              void* d_out, int out_size) {
    const float* pred = (const float*)d_in[0];
    const float* gt   = (const float*)d_in[1];
    const float* vis  = (const float*)d_in[2];
    float* out = (float*)d_out;

    k_zero<<<1, 32>>>();
    k_main<<<(Bn * Nn * CHn) / 256, 256>>>(pred, gt, vis);
    k_id<<<(Nn * 32) / 256, 256>>>();
    k_final<<<1, 1>>>(out);
}